// round 14
// baseline (speedup 1.0000x reference)
#include <cuda_runtime.h>
#include <cuda_fp16.h>
#include <math.h>
#include <stdint.h>

#define N_NODES 100000
#define NP_SCAN 100352           // 98 * 1024 (covers N_NODES+1)
#define NB_SCAN 98
#define ZDIM 64
#define E_TR_MAX 3400000
#define NB_K 26                  // 832 / 32 K-steps for decode GEMM

// ---------------- scratch ----------------
__device__ int   g_hist[N_NODES];
__device__ int   g_rowptr[NP_SCAN];
__device__ int   g_cursor[N_NODES];
__device__ int   g_srclist[E_TR_MAX];
__device__ int   g_bsum[NB_SCAN];
__device__ int   g_boff[NB_SCAN];
__device__ float g_m[N_NODES];
__device__ __half g_yh[N_NODES * ZDIM];  // z1 @ W_rel2 (fp16; R10/R13-proven error-neutral)
__device__ float g_r[N_NODES * ZDIM];
__device__ float g_z2[N_NODES * ZDIM];
__device__ __half g_Bf[128 * 832];       // W1^T fp16, n-major
__device__ __half g_W2f[128 * 128];      // [Wrel2|Wroot2]^T fp16, n-major

// ---------------- PTX helpers ----------------
static __device__ __forceinline__ uint32_t smem_u32(const void* p) {
    uint32_t a;
    asm("{ .reg .u64 t; cvta.to.shared.u64 t, %1; cvt.u32.u64 %0, t; }" : "=r"(a) : "l"(p));
    return a;
}
static __device__ __forceinline__ void ldm_x4(uint32_t* r, uint32_t addr) {
    asm volatile("ldmatrix.sync.aligned.m8n8.x4.shared.b16 {%0,%1,%2,%3}, [%4];"
                 : "=r"(r[0]), "=r"(r[1]), "=r"(r[2]), "=r"(r[3]) : "r"(addr));
}
static __device__ __forceinline__ void mma_f16(float* c, const uint32_t* a,
                                               uint32_t b0, uint32_t b1) {
    asm volatile("mma.sync.aligned.m16n8k16.row.col.f32.f16.f16.f32 "
                 "{%0,%1,%2,%3}, {%4,%5,%6,%7}, {%8,%9}, {%0,%1,%2,%3};"
                 : "+f"(c[0]), "+f"(c[1]), "+f"(c[2]), "+f"(c[3])
                 : "r"(a[0]), "r"(a[1]), "r"(a[2]), "r"(a[3]), "r"(b0), "r"(b1));
}
static __device__ __forceinline__ void cp_async16(uint32_t dst, const void* src) {
    asm volatile("cp.async.cg.shared.global [%0], [%1], 16;" :: "r"(dst), "l"(src));
}
static __device__ __forceinline__ void cp_commit() {
    asm volatile("cp.async.commit_group;");
}
static __device__ __forceinline__ void cp_wait0() {
    asm volatile("cp.async.wait_group 0;" ::: "memory");
}
static __device__ __forceinline__ void cp_wait1() {
    asm volatile("cp.async.wait_group 1;" ::: "memory");
}
static __device__ __forceinline__ void cp_wait2() {
    asm volatile("cp.async.wait_group 2;" ::: "memory");
}

// 8 fp32 -> 8 fp16 (one uint4)
static __device__ __forceinline__ uint4 cvt8h(float4 v0, float4 v1) {
    uint4 o;
    __half2 h0 = __floats2half2_rn(v0.x, v0.y);
    __half2 h1 = __floats2half2_rn(v0.z, v0.w);
    __half2 h2 = __floats2half2_rn(v1.x, v1.y);
    __half2 h3 = __floats2half2_rn(v1.z, v1.w);
    o.x = *(uint32_t*)&h0; o.y = *(uint32_t*)&h1;
    o.z = *(uint32_t*)&h2; o.w = *(uint32_t*)&h3;
    return o;
}

// ================= fused prep: zero hist + W1^T fp16 + W2 fp16 =================
__global__ void prep_k(const float* __restrict__ W1,
                       const float* __restrict__ Wrel2, const float* __restrict__ Wroot2) {
    int i = blockIdx.x * blockDim.x + threadIdx.x;
    if (i < N_NODES) g_hist[i] = 0;
    if (i < 128 * 832) {
        int n = i / 832, k = i % 832;
        g_Bf[i] = __float2half_rn(W1[k * 128 + n]);
    }
    if (i < 128 * 128) {
        int n = i >> 7, k = i & 127;
        float w = (n < 64) ? Wrel2[k * 64 + n] : Wroot2[k * 64 + (n - 64)];
        g_W2f[i] = __float2half_rn(w);
    }
}

// ================= CSR build =================
__global__ void hist_k(const int* __restrict__ dst, int E) {
    int e = blockIdx.x * blockDim.x + threadIdx.x;
    if (e < E) atomicAdd(&g_hist[dst[e]], 1);
}

__global__ void scan1_k() {
    __shared__ int sm[1024];
    int b = blockIdx.x, t = threadIdx.x;
    int i = b * 1024 + t;
    int c = (i < N_NODES) ? g_hist[i] : 0;
    sm[t] = c;
    __syncthreads();
#pragma unroll
    for (int off = 1; off < 1024; off <<= 1) {
        int add = (t >= off) ? sm[t - off] : 0;
        __syncthreads();
        sm[t] += add;
        __syncthreads();
    }
    if (i < NP_SCAN) g_rowptr[i] = sm[t] - c;
    if (t == 1023) g_bsum[b] = sm[1023];
}

__global__ void scan2_k() {
    __shared__ int sm[128];
    int t = threadIdx.x;
    int c = (t < NB_SCAN) ? g_bsum[t] : 0;
    sm[t] = c;
    __syncthreads();
#pragma unroll
    for (int off = 1; off < 128; off <<= 1) {
        int add = (t >= off) ? sm[t - off] : 0;
        __syncthreads();
        sm[t] += add;
        __syncthreads();
    }
    if (t < NB_SCAN) g_boff[t] = sm[t] - c;
}

__global__ void scan3_k() {
    int i = blockIdx.x * blockDim.x + threadIdx.x;
    if (i <= N_NODES) {
        int v = g_rowptr[i] + g_boff[i >> 10];
        g_rowptr[i] = v;
        if (i < N_NODES) g_cursor[i] = v;
    }
}

__global__ void scatter_k(const int* __restrict__ src, const int* __restrict__ dst, int E) {
    int e = blockIdx.x * blockDim.x + threadIdx.x;
    if (e >= E) return;
    int pos = atomicAdd(&g_cursor[dst[e]], 1);
    g_srclist[pos] = src[e];
}

// ================= layer-1 mean gather =================
__global__ void gx_k(const float* __restrict__ x) {
    int w = (blockIdx.x * blockDim.x + threadIdx.x) >> 5;
    int lane = threadIdx.x & 31;
    if (w >= N_NODES) return;
    int start = g_rowptr[w], end = g_rowptr[w + 1];
    float s = 0.0f;
    for (int j = start + lane; j < end; j += 32) s += __ldg(x + g_srclist[j]);
#pragma unroll
    for (int o = 16; o; o >>= 1) s += __shfl_down_sync(0xFFFFFFFFu, s, o);
    if (lane == 0) g_m[w] = s / fmaxf((float)(end - start), 1.0f);
}

// ================= layer-2 gather-reduce + node2 fused =================
__global__ void agg_k(const float* __restrict__ b2) {
    int w = (blockIdx.x * blockDim.x + threadIdx.x) >> 5;
    int lane = threadIdx.x & 31;
    if (w >= N_NODES) return;
    int start = g_rowptr[w], end = g_rowptr[w + 1];
    float2 acc = make_float2(0.0f, 0.0f);
    for (int j0 = start; j0 < end; j0 += 32) {
        int jl = j0 + lane;
        int sj = (jl < end) ? g_srclist[jl] : 0;
        int cnt = end - j0; if (cnt > 32) cnt = 32;
        for (int k = 0; k < cnt; k++) {
            int s = __shfl_sync(0xFFFFFFFFu, sj, k);
            float2 v = __half22float2(*(const __half2*)&g_yh[s * ZDIM + lane * 2]);
            acc.x += v.x; acc.y += v.y;
        }
    }
    float inv = 1.0f / fmaxf((float)(end - start), 1.0f);
    int c = lane * 2;
    float2 r = *(const float2*)&g_r[w * ZDIM + c];
    float2 z;
    z.x = fmaxf(r.x + acc.x * inv + __ldg(b2 + c), 0.0f);
    z.y = fmaxf(r.y + acc.y * inv + __ldg(b2 + c + 1), 0.0f);
    *(float2*)&g_z2[w * ZDIM + c] = z;
}

// ======== node1: single-phase smem, 1 sync; y stored fp16 ========
#define N1_A_STRIDE 272
#define N1_B_OFF 17408
#define N1_SMEM (17408 + 34816)
__global__ __launch_bounds__(256)
void node1_mma_k(const float* __restrict__ x,
                 const float* __restrict__ Wroot1, const float* __restrict__ Wrel1,
                 const float* __restrict__ b1) {
    extern __shared__ __align__(128) char smem[];
    uint32_t sb = smem_u32(smem);
    int tid = threadIdx.x, lane = tid & 31, wid = tid >> 5;
    int wm = wid >> 2, wn = wid & 3;
    int n0 = blockIdx.x * 64;

    {
        int nl = tid >> 2;
        int q  = tid & 3;
        int node = n0 + nl; if (node >= N_NODES) node = N_NODES - 1;
        float xi = x[node];
        float m = g_m[node];
        uint32_t* dst = (uint32_t*)(smem + nl * N1_A_STRIDE + q * 64);
#pragma unroll
        for (int j = 0; j < 16; j++) {
            int c = q * 32 + j * 2;
            float z0  = fmaxf(xi * __ldg(Wroot1 + c)     + m * __ldg(Wrel1 + c)     + __ldg(b1 + c), 0.0f);
            float z1v = fmaxf(xi * __ldg(Wroot1 + c + 1) + m * __ldg(Wrel1 + c + 1) + __ldg(b1 + c + 1), 0.0f);
            __half2 h = __floats2half2_rn(z0, z1v);
            dst[j] = *(uint32_t*)&h;
        }
    }
#pragma unroll
    for (int i = 0; i < 8; i++) {
        int idx = tid + i * 256;
        int row = idx >> 4, ch = idx & 15;
        *(uint4*)(smem + N1_B_OFF + row * N1_A_STRIDE + ch * 16) =
            *(const uint4*)((const char*)g_W2f + (size_t)row * 256 + ch * 16);
    }
    __syncthreads();

    float acc[2][4][4];
#pragma unroll
    for (int a = 0; a < 2; a++)
#pragma unroll
        for (int b = 0; b < 4; b++)
#pragma unroll
            for (int c = 0; c < 4; c++) acc[a][b][c] = 0.0f;

#pragma unroll
    for (int kh = 0; kh < 8; kh++) {
        uint32_t ah[2][4], bh[2][4];
#pragma unroll
        for (int mt = 0; mt < 2; mt++) {
            int row = wm * 32 + mt * 16 + (lane & 15);
            ldm_x4(ah[mt], sb + row * N1_A_STRIDE + kh * 32 + (lane >> 4) * 16);
        }
#pragma unroll
        for (int g = 0; g < 2; g++) {
            int n = wn * 32 + g * 16 + (lane & 15);
            ldm_x4(bh[g], sb + N1_B_OFF + n * N1_A_STRIDE + kh * 32 + (lane >> 4) * 16);
        }
#pragma unroll
        for (int mt = 0; mt < 2; mt++)
#pragma unroll
            for (int g = 0; g < 2; g++)
#pragma unroll
                for (int p = 0; p < 2; p++)
                    mma_f16(acc[mt][g * 2 + p], ah[mt], bh[g][p], bh[g][p + 2]);
    }

#pragma unroll
    for (int mt = 0; mt < 2; mt++)
#pragma unroll
        for (int t8 = 0; t8 < 4; t8++) {
            int r0 = wm * 32 + mt * 16 + (lane >> 2);
            int cb = wn * 32 + t8 * 8 + (lane & 3) * 2;
#pragma unroll
            for (int half = 0; half < 2; half++) {
                int node = n0 + r0 + half * 8;
                if (node < N_NODES) {
                    float v0 = acc[mt][t8][half * 2];
                    float v1 = acc[mt][t8][half * 2 + 1];
                    if (cb < 64) {
                        __half2 h = __floats2half2_rn(v0, v1);
                        *(__half2*)&g_yh[node * 64 + cb] = h;
                    } else {
                        int c = cb - 64;
                        g_r[node * 64 + c]     = v0;
                        g_r[node * 64 + c + 1] = v1;
                    }
                }
            }
        }
}

// ======== decode GEMM v8: CTA 256x128, 1024 thr, 4-stage cp.async, inline pair gather ========
// smem: A32 ring 4x32768 @0 | B ring 4x10240 @131072 | A16 2x20480 @172032  = 212992
// epilogue overlay: Hs fp16 [256][136] (69632B) @0, W2s @69632
#define A32_OFF 0
#define B_OFF   131072
#define A16_OFF 172032
#define W2S_OFF 69632
#define SMEM_DEC 212992

__global__ __launch_bounds__(1024, 1)
void decode_mma_k(const int* __restrict__ esrc_a, const int* __restrict__ edst_a,
                  const float* __restrict__ eattr,
                  const float* __restrict__ bl1, const float* __restrict__ W2,
                  const float* __restrict__ bl2,
                  float* __restrict__ out, int E) {
    extern __shared__ __align__(128) char smem[];
    uint32_t sb = smem_u32(smem);
    int tid = threadIdx.x, lane = tid & 31, wid = tid >> 5;
    int wm = wid >> 2, wn = wid & 3;           // warps 8(M) x 4(N), warp tile 32x32
    int e0 = blockIdx.x * 256;

    float acc[2][4][4];
#pragma unroll
    for (int a = 0; a < 2; a++)
#pragma unroll
        for (int b = 0; b < 4; b++)
#pragma unroll
            for (int c = 0; c < 4; c++) acc[a][b][c] = 0.0f;

    int arow = tid >> 2;         // 0..255
    int aq = tid & 3;
    int ae = e0 + arow; if (ae >= E) ae = E - 1;
    int esrc = esrc_a[ae], edst = edst_a[ae];
    int bn = tid >> 2;           // rows 0..127 (tid<512)
    int bq = tid & 3;

// B-tile cp.async (all kb); A-tile cp.async only for kb>=2 (kb<2 = inline pair gather)
#define ISSUE_B(kb) do {                                                          \
    if (tid < 512) {                                                              \
        const char* bsrc = (const char*)g_Bf + (size_t)bn * 1664 + (size_t)(kb) * 64 + bq * 16; \
        uint32_t bdst = sb + B_OFF + ((kb) & 3) * 10240 + bn * 80 + bq * 16;      \
        cp_async16(bdst, bsrc);                                                   \
    }                                                                             \
} while (0)

#define ISSUE_A(kb) do {                                                          \
    const char* asrc = (const char*)(eattr + (size_t)ae * 768 + ((kb) - 2) * 32 + aq * 8); \
    uint32_t adst = sb + A32_OFF + ((kb) & 3) * 32768 + arow * 128 + aq * 32;     \
    cp_async16(adst,      asrc);                                                  \
    cp_async16(adst + 16, asrc + 16);                                             \
} while (0)

    ISSUE_B(0); cp_commit();
    ISSUE_B(1); cp_commit();
    ISSUE_B(2); ISSUE_A(2); cp_commit();

    for (int kb = 0; kb < NB_K; kb++) {
        int s4 = kb & 3;
        if (kb + 1 >= NB_K) cp_wait0();
        else if (kb + 2 >= NB_K) cp_wait1();
        else cp_wait2();
        // produce A16 for this kb
        {
            float4 v0, v1;
            if (kb >= 2) {
                const char* a32 = smem + A32_OFF + s4 * 32768 + arow * 128 + aq * 32;
                v0 = ((const float4*)a32)[0];
                v1 = ((const float4*)a32)[1];
            } else {
                const float4* ps = (const float4*)(g_z2 + (size_t)esrc * 64 + kb * 32 + aq * 8);
                const float4* pd = (const float4*)(g_z2 + (size_t)edst * 64 + kb * 32 + aq * 8);
                float4 a0 = ps[0], a1 = ps[1];
                float4 b0 = pd[0], b1 = pd[1];
                v0 = make_float4(a0.x * b0.x, a0.y * b0.y, a0.z * b0.z, a0.w * b0.w);
                v1 = make_float4(a1.x * b1.x, a1.y * b1.y, a1.z * b1.z, a1.w * b1.w);
            }
            uint32_t a16 = (uint32_t)(A16_OFF + (kb & 1) * 20480 + arow * 80 + aq * 16);
            *(uint4*)(smem + a16) = cvt8h(v0, v1);
        }
        __syncthreads();
        if (kb + 3 < NB_K) { ISSUE_B(kb + 3); ISSUE_A(kb + 3); cp_commit(); }
        uint32_t a16b = sb + A16_OFF + (kb & 1) * 20480;
        uint32_t bbase = sb + B_OFF + s4 * 10240;
#pragma unroll
        for (int kh = 0; kh < 2; kh++) {
            uint32_t ah[2][4], bh[2][4];
#pragma unroll
            for (int mt = 0; mt < 2; mt++) {
                int row = wm * 32 + mt * 16 + (lane & 15);
                ldm_x4(ah[mt], a16b + row * 80 + kh * 32 + (lane >> 4) * 16);
            }
#pragma unroll
            for (int g = 0; g < 2; g++) {
                int n = wn * 32 + g * 16 + (lane & 15);
                ldm_x4(bh[g], bbase + n * 80 + kh * 32 + (lane >> 4) * 16);
            }
#pragma unroll
            for (int mt = 0; mt < 2; mt++)
#pragma unroll
                for (int g = 0; g < 2; g++)
#pragma unroll
                    for (int p = 0; p < 2; p++)
                        mma_f16(acc[mt][g * 2 + p], ah[mt], bh[g][p], bh[g][p + 2]);
        }
    }
    __syncthreads();

    // epilogue: Hs fp16 [256][136 halves], W2s fp32 (645)
    __half* Hs = (__half*)smem;
    float* W2s = (float*)(smem + W2S_OFF);
#pragma unroll
    for (int mt = 0; mt < 2; mt++)
#pragma unroll
        for (int g = 0; g < 2; g++)
#pragma unroll
            for (int p = 0; p < 2; p++) {
                int r0 = wm * 32 + mt * 16 + (lane >> 2);
                int cb = wn * 32 + g * 16 + p * 8 + (lane & 3) * 2;
                float b0 = __ldg(bl1 + cb), b1 = __ldg(bl1 + cb + 1);
                float* c = acc[mt][g * 2 + p];
                __half2 lo = __floats2half2_rn(fmaxf(c[0] + b0, 0.0f), fmaxf(c[1] + b1, 0.0f));
                __half2 hi = __floats2half2_rn(fmaxf(c[2] + b0, 0.0f), fmaxf(c[3] + b1, 0.0f));
                *(__half2*)&Hs[r0 * 136 + cb]       = lo;
                *(__half2*)&Hs[(r0 + 8) * 136 + cb] = hi;
            }
    for (int i = tid; i < 645; i += 1024) W2s[i] = (i < 640) ? __ldg(W2 + i) : __ldg(bl2 + i - 640);
    __syncthreads();

    if (tid < 256) {
        int e = e0 + tid;
        if (e < E) {
            float l[5];
#pragma unroll
            for (int q = 0; q < 5; q++) l[q] = W2s[640 + q];
#pragma unroll 4
            for (int k2 = 0; k2 < 64; k2++) {
                __half2 hv = *(__half2*)&Hs[tid * 136 + k2 * 2];
                float2 f = __half22float2(hv);
#pragma unroll
                for (int q = 0; q < 5; q++)
                    l[q] += f.x * W2s[(k2 * 2) * 5 + q] + f.y * W2s[(k2 * 2 + 1) * 5 + q];
            }
            float mx = l[0];
#pragma unroll
            for (int q = 1; q < 5; q++) mx = fmaxf(mx, l[q]);
            float s = 0.0f, ex[5];
#pragma unroll
            for (int q = 0; q < 5; q++) { ex[q] = expf(l[q] - mx); s += ex[q]; }
            float inv = 1.0f / s;
#pragma unroll
            for (int q = 0; q < 5; q++) out[e * 5 + q] = ex[q] * inv;
        }
    }
}

extern "C" void kernel_launch(void* const* d_in, const int* in_sizes, int n_in,
                              void* d_out, int out_size) {
    const float* x      = (const float*)d_in[0];
    const int*   tei    = (const int*)d_in[1];
    const int*   dei    = (const int*)d_in[2];
    const float* eattr  = (const float*)d_in[3];
    const float* Wroot1 = (const float*)d_in[4];
    const float* Wrel1  = (const float*)d_in[5];
    const float* b1     = (const float*)d_in[6];
    const float* Wroot2 = (const float*)d_in[7];
    const float* Wrel2  = (const float*)d_in[8];
    const float* b2     = (const float*)d_in[9];
    const float* W1     = (const float*)d_in[10];
    const float* bl1    = (const float*)d_in[11];
    const float* W2     = (const float*)d_in[12];
    const float* bl2    = (const float*)d_in[13];
    float* out = (float*)d_out;

    int Etr = in_sizes[1] / 2;
    int Ed  = in_sizes[2] / 2;

    static int smem_set = 0;
    if (!smem_set) {
        cudaFuncSetAttribute(decode_mma_k, cudaFuncAttributeMaxDynamicSharedMemorySize,
                             SMEM_DEC);
        cudaFuncSetAttribute(node1_mma_k, cudaFuncAttributeMaxDynamicSharedMemorySize,
                             N1_SMEM);
        smem_set = 1;
    }

    const int* tsrc = tei;
    const int* tdst = tei + Etr;

    // prep (hist zero + weight conversions) + CSR build
    prep_k<<<(128 * 832 + 255) / 256, 256>>>(W1, Wrel2, Wroot2);
    hist_k<<<(Etr + 255) / 256, 256>>>(tdst, Etr);
    scan1_k<<<NB_SCAN, 1024>>>();
    scan2_k<<<1, 128>>>();
    scan3_k<<<(NP_SCAN + 255) / 256, 256>>>();
    scatter_k<<<(Etr + 255) / 256, 256>>>(tsrc, tdst, Etr);

    // layer 1
    gx_k<<<(N_NODES + 7) / 8, 256>>>(x);
    node1_mma_k<<<(N_NODES + 63) / 64, 256, N1_SMEM>>>(x, Wroot1, Wrel1, b1);

    // layer 2 (gather-reduce, fused node2)
    agg_k<<<(N_NODES + 7) / 8, 256>>>(b2);

    // decode (pair gather fused into kb<2)
    decode_mma_k<<<(Ed + 255) / 256, 1024, SMEM_DEC>>>(dei, dei + Ed, eattr,
                                                       bl1, W2, bl2, out, Ed);
}

// round 15
// speedup vs baseline: 1.0710x; 1.0710x over previous
#include <cuda_runtime.h>
#include <cuda_fp16.h>
#include <math.h>
#include <stdint.h>

#define N_NODES 100000
#define NP_SCAN 100352           // 98 * 1024 (covers N_NODES+1)
#define NB_SCAN 98
#define ZDIM 64
#define E_TR_MAX 3400000
#define E_DEC_MAX 200000
#define NB_K 26                  // 832 / 32 K-steps for decode GEMM

// ---------------- scratch ----------------
__device__ int   g_hist[N_NODES];
__device__ int   g_rowptr[NP_SCAN];
__device__ int   g_cursor[N_NODES];
__device__ int   g_srclist[E_TR_MAX];
__device__ int   g_bsum[NB_SCAN];
__device__ int   g_boff[NB_SCAN];
__device__ float g_m[N_NODES];
__device__ __half g_yh[N_NODES * ZDIM];  // z1 @ W_rel2 (fp16; proven error-neutral)
__device__ float g_r[N_NODES * ZDIM];
__device__ float g_z2[N_NODES * ZDIM];
__device__ float g_nrep[E_DEC_MAX * ZDIM];
__device__ __half g_Bf[128 * 832];       // W1^T fp16, n-major
__device__ __half g_W2f[128 * 128];      // [Wrel2|Wroot2]^T fp16, n-major

// ---------------- PTX helpers ----------------
static __device__ __forceinline__ uint32_t smem_u32(const void* p) {
    uint32_t a;
    asm("{ .reg .u64 t; cvta.to.shared.u64 t, %1; cvt.u32.u64 %0, t; }" : "=r"(a) : "l"(p));
    return a;
}
static __device__ __forceinline__ void ldm_x4(uint32_t* r, uint32_t addr) {
    asm volatile("ldmatrix.sync.aligned.m8n8.x4.shared.b16 {%0,%1,%2,%3}, [%4];"
                 : "=r"(r[0]), "=r"(r[1]), "=r"(r[2]), "=r"(r[3]) : "r"(addr));
}
static __device__ __forceinline__ void mma_f16(float* c, const uint32_t* a,
                                               uint32_t b0, uint32_t b1) {
    asm volatile("mma.sync.aligned.m16n8k16.row.col.f32.f16.f16.f32 "
                 "{%0,%1,%2,%3}, {%4,%5,%6,%7}, {%8,%9}, {%0,%1,%2,%3};"
                 : "+f"(c[0]), "+f"(c[1]), "+f"(c[2]), "+f"(c[3])
                 : "r"(a[0]), "r"(a[1]), "r"(a[2]), "r"(a[3]), "r"(b0), "r"(b1));
}
static __device__ __forceinline__ void cp_async16(uint32_t dst, const void* src) {
    asm volatile("cp.async.cg.shared.global [%0], [%1], 16;" :: "r"(dst), "l"(src));
}
static __device__ __forceinline__ void cp_commit() {
    asm volatile("cp.async.commit_group;");
}
static __device__ __forceinline__ void cp_wait0() {
    asm volatile("cp.async.wait_group 0;" ::: "memory");
}
static __device__ __forceinline__ void cp_wait1() {
    asm volatile("cp.async.wait_group 1;" ::: "memory");
}
static __device__ __forceinline__ void cp_wait2() {
    asm volatile("cp.async.wait_group 2;" ::: "memory");
}

// 8 fp32 -> 8 fp16 (one uint4)
static __device__ __forceinline__ uint4 cvt8h(float4 v0, float4 v1) {
    uint4 o;
    __half2 h0 = __floats2half2_rn(v0.x, v0.y);
    __half2 h1 = __floats2half2_rn(v0.z, v0.w);
    __half2 h2 = __floats2half2_rn(v1.x, v1.y);
    __half2 h3 = __floats2half2_rn(v1.z, v1.w);
    o.x = *(uint32_t*)&h0; o.y = *(uint32_t*)&h1;
    o.z = *(uint32_t*)&h2; o.w = *(uint32_t*)&h3;
    return o;
}

// ================= fused prep: zero hist + W1^T fp16 + W2 fp16 =================
__global__ void prep_k(const float* __restrict__ W1,
                       const float* __restrict__ Wrel2, const float* __restrict__ Wroot2) {
    int i = blockIdx.x * blockDim.x + threadIdx.x;
    if (i < N_NODES) g_hist[i] = 0;
    if (i < 128 * 832) {
        int n = i / 832, k = i % 832;
        g_Bf[i] = __float2half_rn(W1[k * 128 + n]);
    }
    if (i < 128 * 128) {
        int n = i >> 7, k = i & 127;
        float w = (n < 64) ? Wrel2[k * 64 + n] : Wroot2[k * 64 + (n - 64)];
        g_W2f[i] = __float2half_rn(w);
    }
}

// ================= CSR build =================
__global__ void hist_k(const int* __restrict__ dst, int E) {
    int e = blockIdx.x * blockDim.x + threadIdx.x;
    if (e < E) atomicAdd(&g_hist[dst[e]], 1);
}

__global__ void scan1_k() {
    __shared__ int sm[1024];
    int b = blockIdx.x, t = threadIdx.x;
    int i = b * 1024 + t;
    int c = (i < N_NODES) ? g_hist[i] : 0;
    sm[t] = c;
    __syncthreads();
#pragma unroll
    for (int off = 1; off < 1024; off <<= 1) {
        int add = (t >= off) ? sm[t - off] : 0;
        __syncthreads();
        sm[t] += add;
        __syncthreads();
    }
    if (i < NP_SCAN) g_rowptr[i] = sm[t] - c;
    if (t == 1023) g_bsum[b] = sm[1023];
}

__global__ void scan2_k() {
    __shared__ int sm[128];
    int t = threadIdx.x;
    int c = (t < NB_SCAN) ? g_bsum[t] : 0;
    sm[t] = c;
    __syncthreads();
#pragma unroll
    for (int off = 1; off < 128; off <<= 1) {
        int add = (t >= off) ? sm[t - off] : 0;
        __syncthreads();
        sm[t] += add;
        __syncthreads();
    }
    if (t < NB_SCAN) g_boff[t] = sm[t] - c;
}

__global__ void scan3_k() {
    int i = blockIdx.x * blockDim.x + threadIdx.x;
    if (i <= N_NODES) {
        int v = g_rowptr[i] + g_boff[i >> 10];
        g_rowptr[i] = v;
        if (i < N_NODES) g_cursor[i] = v;
    }
}

__global__ void scatter_k(const int* __restrict__ src, const int* __restrict__ dst, int E) {
    int e = blockIdx.x * blockDim.x + threadIdx.x;
    if (e >= E) return;
    int pos = atomicAdd(&g_cursor[dst[e]], 1);
    g_srclist[pos] = src[e];
}

// ================= layer-1 mean gather =================
__global__ void gx_k(const float* __restrict__ x) {
    int w = (blockIdx.x * blockDim.x + threadIdx.x) >> 5;
    int lane = threadIdx.x & 31;
    if (w >= N_NODES) return;
    int start = g_rowptr[w], end = g_rowptr[w + 1];
    float s = 0.0f;
    for (int j = start + lane; j < end; j += 32) s += __ldg(x + g_srclist[j]);
#pragma unroll
    for (int o = 16; o; o >>= 1) s += __shfl_down_sync(0xFFFFFFFFu, s, o);
    if (lane == 0) g_m[w] = s / fmaxf((float)(end - start), 1.0f);
}

// ================= layer-2 gather-reduce + node2 fused =================
__global__ void agg_k(const float* __restrict__ b2) {
    int w = (blockIdx.x * blockDim.x + threadIdx.x) >> 5;
    int lane = threadIdx.x & 31;
    if (w >= N_NODES) return;
    int start = g_rowptr[w], end = g_rowptr[w + 1];
    float2 acc = make_float2(0.0f, 0.0f);
    for (int j0 = start; j0 < end; j0 += 32) {
        int jl = j0 + lane;
        int sj = (jl < end) ? g_srclist[jl] : 0;
        int cnt = end - j0; if (cnt > 32) cnt = 32;
        for (int k = 0; k < cnt; k++) {
            int s = __shfl_sync(0xFFFFFFFFu, sj, k);
            float2 v = __half22float2(*(const __half2*)&g_yh[s * ZDIM + lane * 2]);
            acc.x += v.x; acc.y += v.y;
        }
    }
    float inv = 1.0f / fmaxf((float)(end - start), 1.0f);
    int c = lane * 2;
    float2 r = *(const float2*)&g_r[w * ZDIM + c];
    float2 z;
    z.x = fmaxf(r.x + acc.x * inv + __ldg(b2 + c), 0.0f);
    z.y = fmaxf(r.y + acc.y * inv + __ldg(b2 + c + 1), 0.0f);
    *(float2*)&g_z2[w * ZDIM + c] = z;
}

// ---------------- decode pair gather ----------------
__global__ void pair_k(const int* __restrict__ src, const int* __restrict__ dst, int E) {
    int idx = blockIdx.x * blockDim.x + threadIdx.x;
    int e = idx >> 4;
    if (e >= E) return;
    int g = idx & 15;
    int s = src[e], d = dst[e];
    float4 a = ((const float4*)g_z2)[s * 16 + g];
    float4 b = ((const float4*)g_z2)[d * 16 + g];
    float4 o;
    o.x = a.x * b.x; o.y = a.y * b.y; o.z = a.z * b.z; o.w = a.w * b.w;
    ((float4*)g_nrep)[e * 16 + g] = o;
}

// ======== node1: single-phase smem, 1 sync; y stored fp16 ========
#define N1_A_STRIDE 272
#define N1_B_OFF 17408
#define N1_SMEM (17408 + 34816)
__global__ __launch_bounds__(256)
void node1_mma_k(const float* __restrict__ x,
                 const float* __restrict__ Wroot1, const float* __restrict__ Wrel1,
                 const float* __restrict__ b1) {
    extern __shared__ __align__(128) char smem[];
    uint32_t sb = smem_u32(smem);
    int tid = threadIdx.x, lane = tid & 31, wid = tid >> 5;
    int wm = wid >> 2, wn = wid & 3;
    int n0 = blockIdx.x * 64;

    {
        int nl = tid >> 2;
        int q  = tid & 3;
        int node = n0 + nl; if (node >= N_NODES) node = N_NODES - 1;
        float xi = x[node];
        float m = g_m[node];
        uint32_t* dst = (uint32_t*)(smem + nl * N1_A_STRIDE + q * 64);
#pragma unroll
        for (int j = 0; j < 16; j++) {
            int c = q * 32 + j * 2;
            float z0  = fmaxf(xi * __ldg(Wroot1 + c)     + m * __ldg(Wrel1 + c)     + __ldg(b1 + c), 0.0f);
            float z1v = fmaxf(xi * __ldg(Wroot1 + c + 1) + m * __ldg(Wrel1 + c + 1) + __ldg(b1 + c + 1), 0.0f);
            __half2 h = __floats2half2_rn(z0, z1v);
            dst[j] = *(uint32_t*)&h;
        }
    }
#pragma unroll
    for (int i = 0; i < 8; i++) {
        int idx = tid + i * 256;
        int row = idx >> 4, ch = idx & 15;
        *(uint4*)(smem + N1_B_OFF + row * N1_A_STRIDE + ch * 16) =
            *(const uint4*)((const char*)g_W2f + (size_t)row * 256 + ch * 16);
    }
    __syncthreads();

    float acc[2][4][4];
#pragma unroll
    for (int a = 0; a < 2; a++)
#pragma unroll
        for (int b = 0; b < 4; b++)
#pragma unroll
            for (int c = 0; c < 4; c++) acc[a][b][c] = 0.0f;

#pragma unroll
    for (int kh = 0; kh < 8; kh++) {
        uint32_t ah[2][4], bh[2][4];
#pragma unroll
        for (int mt = 0; mt < 2; mt++) {
            int row = wm * 32 + mt * 16 + (lane & 15);
            ldm_x4(ah[mt], sb + row * N1_A_STRIDE + kh * 32 + (lane >> 4) * 16);
        }
#pragma unroll
        for (int g = 0; g < 2; g++) {
            int n = wn * 32 + g * 16 + (lane & 15);
            ldm_x4(bh[g], sb + N1_B_OFF + n * N1_A_STRIDE + kh * 32 + (lane >> 4) * 16);
        }
#pragma unroll
        for (int mt = 0; mt < 2; mt++)
#pragma unroll
            for (int g = 0; g < 2; g++)
#pragma unroll
                for (int p = 0; p < 2; p++)
                    mma_f16(acc[mt][g * 2 + p], ah[mt], bh[g][p], bh[g][p + 2]);
    }

#pragma unroll
    for (int mt = 0; mt < 2; mt++)
#pragma unroll
        for (int t8 = 0; t8 < 4; t8++) {
            int r0 = wm * 32 + mt * 16 + (lane >> 2);
            int cb = wn * 32 + t8 * 8 + (lane & 3) * 2;
#pragma unroll
            for (int half = 0; half < 2; half++) {
                int node = n0 + r0 + half * 8;
                if (node < N_NODES) {
                    float v0 = acc[mt][t8][half * 2];
                    float v1 = acc[mt][t8][half * 2 + 1];
                    if (cb < 64) {
                        __half2 h = __floats2half2_rn(v0, v1);
                        *(__half2*)&g_yh[node * 64 + cb] = h;
                    } else {
                        int c = cb - 64;
                        g_r[node * 64 + c]     = v0;
                        g_r[node * 64 + c + 1] = v1;
                    }
                }
            }
        }
}

// ======== decode GEMM (R13-proven): CTA 256x128, 1024 thr, 4-stage cp.async depth-3 ========
// smem: A32 ring 4x32768 @0 | B ring 4x10240 @131072 | A16 2x20480 @172032  = 212992
// epilogue overlay: Hs fp16 [256][136] (69632B) @0, W2s @69632
#define A32_OFF 0
#define B_OFF   131072
#define A16_OFF 172032
#define W2S_OFF 69632
#define SMEM_DEC 212992

__global__ __launch_bounds__(1024, 1)
void decode_mma_k(const float* __restrict__ eattr,
                  const float* __restrict__ bl1, const float* __restrict__ W2,
                  const float* __restrict__ bl2,
                  float* __restrict__ out, int E) {
    extern __shared__ __align__(128) char smem[];
    uint32_t sb = smem_u32(smem);
    int tid = threadIdx.x, lane = tid & 31, wid = tid >> 5;
    int wm = wid >> 2, wn = wid & 3;           // warps 8(M) x 4(N), warp tile 32x32
    int e0 = blockIdx.x * 256;

    float acc[2][4][4];
#pragma unroll
    for (int a = 0; a < 2; a++)
#pragma unroll
        for (int b = 0; b < 4; b++)
#pragma unroll
            for (int c = 0; c < 4; c++) acc[a][b][c] = 0.0f;

    int arow = tid >> 2;         // 0..255
    int aq = tid & 3;
    int ae = e0 + arow; if (ae >= E) ae = E - 1;
    int bn = tid >> 2;           // rows 0..127 (tid<512)
    int bq = tid & 3;

#define ISSUE(kb) do {                                                            \
    int _s = (kb) & 3;                                                            \
    const char* asrc = ((kb) < 2)                                                 \
        ? (const char*)(g_nrep + (size_t)ae * 64 + (kb) * 32 + aq * 8)            \
        : (const char*)(eattr + (size_t)ae * 768 + ((kb) - 2) * 32 + aq * 8);     \
    uint32_t adst = sb + A32_OFF + _s * 32768 + arow * 128 + aq * 32;             \
    cp_async16(adst,      asrc);                                                  \
    cp_async16(adst + 16, asrc + 16);                                             \
    if (tid < 512) {                                                              \
        const char* bsrc = (const char*)g_Bf + (size_t)bn * 1664 + (size_t)(kb) * 64 + bq * 16; \
        uint32_t bdst = sb + B_OFF + _s * 10240 + bn * 80 + bq * 16;              \
        cp_async16(bdst, bsrc);                                                   \
    }                                                                             \
    cp_commit();                                                                  \
} while (0)

    ISSUE(0);
    ISSUE(1);
    ISSUE(2);

    for (int kb = 0; kb < NB_K; kb++) {
        int s4 = kb & 3;
        if (kb + 1 >= NB_K) cp_wait0();
        else if (kb + 2 >= NB_K) cp_wait1();
        else cp_wait2();
        // convert own A32 bytes -> A16
        {
            const char* a32 = smem + A32_OFF + s4 * 32768 + arow * 128 + aq * 32;
            float4 v0 = ((const float4*)a32)[0];
            float4 v1 = ((const float4*)a32)[1];
            uint32_t a16 = (uint32_t)(A16_OFF + (kb & 1) * 20480 + arow * 80 + aq * 16);
            *(uint4*)(smem + a16) = cvt8h(v0, v1);
        }
        __syncthreads();
        if (kb + 3 < NB_K) ISSUE(kb + 3);
        uint32_t a16b = sb + A16_OFF + (kb & 1) * 20480;
        uint32_t bbase = sb + B_OFF + s4 * 10240;
#pragma unroll
        for (int kh = 0; kh < 2; kh++) {
            uint32_t ah[2][4], bh[2][4];
#pragma unroll
            for (int mt = 0; mt < 2; mt++) {
                int row = wm * 32 + mt * 16 + (lane & 15);
                ldm_x4(ah[mt], a16b + row * 80 + kh * 32 + (lane >> 4) * 16);
            }
#pragma unroll
            for (int g = 0; g < 2; g++) {
                int n = wn * 32 + g * 16 + (lane & 15);
                ldm_x4(bh[g], bbase + n * 80 + kh * 32 + (lane >> 4) * 16);
            }
#pragma unroll
            for (int mt = 0; mt < 2; mt++)
#pragma unroll
                for (int g = 0; g < 2; g++)
#pragma unroll
                    for (int p = 0; p < 2; p++)
                        mma_f16(acc[mt][g * 2 + p], ah[mt], bh[g][p], bh[g][p + 2]);
        }
    }
    __syncthreads();

    // epilogue: Hs fp16 [256][136 halves], W2s fp32 (645)
    __half* Hs = (__half*)smem;
    float* W2s = (float*)(smem + W2S_OFF);
#pragma unroll
    for (int mt = 0; mt < 2; mt++)
#pragma unroll
        for (int g = 0; g < 2; g++)
#pragma unroll
            for (int p = 0; p < 2; p++) {
                int r0 = wm * 32 + mt * 16 + (lane >> 2);
                int cb = wn * 32 + g * 16 + p * 8 + (lane & 3) * 2;
                float b0 = __ldg(bl1 + cb), b1 = __ldg(bl1 + cb + 1);
                float* c = acc[mt][g * 2 + p];
                __half2 lo = __floats2half2_rn(fmaxf(c[0] + b0, 0.0f), fmaxf(c[1] + b1, 0.0f));
                __half2 hi = __floats2half2_rn(fmaxf(c[2] + b0, 0.0f), fmaxf(c[3] + b1, 0.0f));
                *(__half2*)&Hs[r0 * 136 + cb]       = lo;
                *(__half2*)&Hs[(r0 + 8) * 136 + cb] = hi;
            }
    for (int i = tid; i < 645; i += 1024) W2s[i] = (i < 640) ? __ldg(W2 + i) : __ldg(bl2 + i - 640);
    __syncthreads();

    if (tid < 256) {
        int e = e0 + tid;
        if (e < E) {
            float l[5];
#pragma unroll
            for (int q = 0; q < 5; q++) l[q] = W2s[640 + q];
#pragma unroll 4
            for (int k2 = 0; k2 < 64; k2++) {
                __half2 hv = *(__half2*)&Hs[tid * 136 + k2 * 2];
                float2 f = __half22float2(hv);
#pragma unroll
                for (int q = 0; q < 5; q++)
                    l[q] += f.x * W2s[(k2 * 2) * 5 + q] + f.y * W2s[(k2 * 2 + 1) * 5 + q];
            }
            float mx = l[0];
#pragma unroll
            for (int q = 1; q < 5; q++) mx = fmaxf(mx, l[q]);
            float s = 0.0f, ex[5];
#pragma unroll
            for (int q = 0; q < 5; q++) { ex[q] = expf(l[q] - mx); s += ex[q]; }
            float inv = 1.0f / s;
#pragma unroll
            for (int q = 0; q < 5; q++) out[e * 5 + q] = ex[q] * inv;
        }
    }
}

extern "C" void kernel_launch(void* const* d_in, const int* in_sizes, int n_in,
                              void* d_out, int out_size) {
    const float* x      = (const float*)d_in[0];
    const int*   tei    = (const int*)d_in[1];
    const int*   dei    = (const int*)d_in[2];
    const float* eattr  = (const float*)d_in[3];
    const float* Wroot1 = (const float*)d_in[4];
    const float* Wrel1  = (const float*)d_in[5];
    const float* b1     = (const float*)d_in[6];
    const float* Wroot2 = (const float*)d_in[7];
    const float* Wrel2  = (const float*)d_in[8];
    const float* b2     = (const float*)d_in[9];
    const float* W1     = (const float*)d_in[10];
    const float* bl1    = (const float*)d_in[11];
    const float* W2     = (const float*)d_in[12];
    const float* bl2    = (const float*)d_in[13];
    float* out = (float*)d_out;

    int Etr = in_sizes[1] / 2;
    int Ed  = in_sizes[2] / 2;

    static int smem_set = 0;
    if (!smem_set) {
        cudaFuncSetAttribute(decode_mma_k, cudaFuncAttributeMaxDynamicSharedMemorySize,
                             SMEM_DEC);
        cudaFuncSetAttribute(node1_mma_k, cudaFuncAttributeMaxDynamicSharedMemorySize,
                             N1_SMEM);
        smem_set = 1;
    }

    const int* tsrc = tei;
    const int* tdst = tei + Etr;

    // prep (hist zero + weight conversions) + CSR build
    prep_k<<<(128 * 832 + 255) / 256, 256>>>(W1, Wrel2, Wroot2);
    hist_k<<<(Etr + 255) / 256, 256>>>(tdst, Etr);
    scan1_k<<<NB_SCAN, 1024>>>();
    scan2_k<<<1, 128>>>();
    scan3_k<<<(NP_SCAN + 255) / 256, 256>>>();
    scatter_k<<<(Etr + 255) / 256, 256>>>(tsrc, tdst, Etr);

    // layer 1
    gx_k<<<(N_NODES + 7) / 8, 256>>>(x);
    node1_mma_k<<<(N_NODES + 63) / 64, 256, N1_SMEM>>>(x, Wroot1, Wrel1, b1);

    // layer 2 (gather-reduce, fused node2)
    agg_k<<<(N_NODES + 7) / 8, 256>>>(b2);

    // decode
    {
        long threads = (long)Ed * 16;
        pair_k<<<(int)((threads + 255) / 256), 256>>>(dei, dei + Ed, Ed);
    }
    decode_mma_k<<<(Ed + 255) / 256, 1024, SMEM_DEC>>>(eattr, bl1, W2, bl2, out, Ed);
}